// round 16
// baseline (speedup 1.0000x reference)
#include <cuda_runtime.h>
#include <cuda_fp16.h>
#include <cstdint>
#include <cstddef>

#define NN   50000
#define EE   800000
#define DIN  128
#define DH   256
#define NBLK ((NN + 255) / 256)   // 196 scan blocks

#define DEG_MASK  ((1ull << 40) - 1ull)
#define CNT_ONE   (1ull << 40)
#define DEG_SCALE 16777216.0f     // 2^24

// ---------------- scratch (device globals; zero-initialized at load) ---------
__device__ unsigned long long g_packed[NN];   // cnt<<40 | fixedpoint(deg); self-reset in scan
__device__ float    g_dinv[NN];           // rsqrt(deg+1)
__device__ int      g_rowstart[NN + 1];   // CSR offsets
__device__ uint2    g_stage[EE];          // (src | dst<<16, rank)
__device__ unsigned g_csru[EE];           // (src<<16) | fp16(w*dinv[s])
__device__ __half   g_xh[NN * DIN];       // x in fp16
__device__ __half   g_a1h[NN * DIN];      // A @ x in fp16
__device__ __half   g_ph[NN * DIN];       // fused-MLP output fp16
__device__ __half   g_w1h[DH * DIN];      // W1 fp16
__device__ __half   g_w2h[DIN * DH];      // W2 fp16
__device__ int      g_ticket;             // lookback ticket (self-reset)
__device__ int      g_done;               // scan completion counter (self-reset)
__device__ unsigned long long g_state[NBLK];  // value<<2 | flag (self-reset)

// ------- fused: fp16 conversions + degree/count/rank staging -----------------
// g_packed assumed zero on entry (zero-init first call; scan resets thereafter).
__global__ void convert_prep_kernel(const void* __restrict__ raw,
                                    const float* __restrict__ w,
                                    const float* __restrict__ x,
                                    const float* __restrict__ W1,
                                    const float* __restrict__ W2,
                                    unsigned long long* __restrict__ pk,
                                    uint2* __restrict__ stage, int e) {
    // per-block dtype detect (int64 LE -> odd int32 words all zero)
    __shared__ int s_is64;
    {
        const int* ri = (const int*)raw;
        int odd = (threadIdx.x < 128) ? ri[2 * threadIdx.x + 1] : 0;
        int any = __syncthreads_or(odd != 0);
        if (threadIdx.x == 0) s_is64 = any ? 0 : 1;
        __syncthreads();
    }
    const int is64   = s_is64;
    const int gtid   = blockIdx.x * blockDim.x + threadIdx.x;
    const int stride = gridDim.x * blockDim.x;

    // fp16 conversions (grid-stride)
    {
        const int pairs = NN * DIN / 2;
        const float2* xin = (const float2*)x;
        __half2* xo = (__half2*)g_xh;
        for (int i = gtid; i < pairs; i += stride) {
            float2 v = xin[i];
            xo[i] = __floats2half2_rn(v.x, v.y);
        }
        const int wp = DH * DIN / 2;
        const float2* w1in = (const float2*)W1;
        const float2* w2in = (const float2*)W2;
        __half2* w1o = (__half2*)g_w1h;
        __half2* w2o = (__half2*)g_w2h;
        for (int i = gtid; i < wp; i += stride) {
            float2 a = w1in[i];
            float2 b = w2in[i];
            w1o[i] = __floats2half2_rn(a.x, a.y);
            w2o[i] = __floats2half2_rn(b.x, b.y);
        }
    }

    // edges (grid-stride, 2 per step)
    for (int base = gtid * 2; base < e; base += stride * 2) {
        int s0, d0;
        if (is64) {
            const long long* p = (const long long*)raw;
            s0 = (int)p[base];
            d0 = (int)p[(size_t)e + base];
        } else {
            const int* p = (const int*)raw;
            s0 = p[base];
            d0 = p[e + base];
        }
        float w0 = w[base];
        unsigned long long c0 = CNT_ONE |
            (unsigned long long)(unsigned)__float2uint_rn(w0 * DEG_SCALE);
        unsigned long long o0 = atomicAdd(&pk[d0], c0);
        stage[base] = make_uint2((unsigned)s0 | ((unsigned)d0 << 16),
                                 (unsigned)(o0 >> 40));
        if (base + 1 < e) {
            int s1, d1;
            if (is64) {
                const long long* p = (const long long*)raw;
                s1 = (int)p[base + 1];
                d1 = (int)p[(size_t)e + base + 1];
            } else {
                const int* p = (const int*)raw;
                s1 = p[base + 1];
                d1 = p[e + base + 1];
            }
            float w1 = w[base + 1];
            unsigned long long c1 = CNT_ONE |
                (unsigned long long)(unsigned)__float2uint_rn(w1 * DEG_SCALE);
            unsigned long long o1 = atomicAdd(&pk[d1], c1);
            stage[base + 1] = make_uint2((unsigned)s1 | ((unsigned)d1 << 16),
                                         (unsigned)(o1 >> 40));
        }
    }
}

// ---------------- single-pass lookback scan (+dinv, self-resetting) ----------
__device__ __forceinline__ int block_scan_incl(int v) {
    const int lane = threadIdx.x & 31;
    const int warp = threadIdx.x >> 5;
    int s = v;
#pragma unroll
    for (int o = 1; o < 32; o <<= 1) {
        int t = __shfl_up_sync(0xFFFFFFFFu, s, o);
        if (lane >= o) s += t;
    }
    __shared__ int wsum[8];
    if (lane == 31) wsum[warp] = s;
    __syncthreads();
    if (warp == 0 && lane < 8) {
        int ws = wsum[lane];
#pragma unroll
        for (int o = 1; o < 8; o <<= 1) {
            int t = __shfl_up_sync(0xFFu, ws, o);
            if (lane >= o) ws += t;
        }
        wsum[lane] = ws;
    }
    __syncthreads();
    return s + (warp > 0 ? wsum[warp - 1] : 0);
}

__global__ void scan_lookback_kernel(unsigned long long* __restrict__ pk,
                                     float* __restrict__ dinv,
                                     int* __restrict__ rowstart, int n) {
    __shared__ int s_bid, s_total, s_excl;
    if (threadIdx.x == 0) s_bid = atomicAdd(&g_ticket, 1);
    __syncthreads();
    const int bid = s_bid;
    const int idx = bid * 256 + threadIdx.x;

    unsigned long long pv = (idx < n) ? pk[idx] : 0ull;
    if (idx < n) pk[idx] = 0ull;              // reset for next replay
    int v = (int)(pv >> 40);
    int incl = block_scan_incl(v);
    if (threadIdx.x == 255) s_total = incl;
    __syncthreads();

    if (threadIdx.x == 0) {
        volatile unsigned long long* st = g_state;
        unsigned long long p =
            ((unsigned long long)s_total << 2) | (bid == 0 ? 2ull : 1ull);
        __threadfence();
        st[bid] = p;
        int excl = 0;
        if (bid > 0) {
            int j = bid - 1;
            while (true) {
                unsigned long long sv = st[j];
                unsigned f = (unsigned)(sv & 3ull);
                if (f == 0) continue;
                excl += (int)(sv >> 2);
                if (f == 2) break;
                j--;
            }
            unsigned long long p2 =
                ((unsigned long long)(excl + s_total) << 2) | 2ull;
            __threadfence();
            st[bid] = p2;
        }
        s_excl = excl;
    }
    __syncthreads();

    const int base = s_excl;
    if (idx < n) {
        rowstart[idx] = base + incl - v;
        float deg = (float)(pv & DEG_MASK) * (1.0f / DEG_SCALE);
        dinv[idx] = rsqrtf(deg + 1.0f);   // +1 = self-loop
    }
    if (bid == (n + 255) / 256 - 1 && threadIdx.x == 255)
        rowstart[n] = base + s_total;

    // self-reset of scan state: last block to finish (all lookback reads done)
    __syncthreads();
    if (threadIdx.x == 0) {
        __threadfence();
        int dcount = atomicAdd(&g_done, 1);
        if (dcount == NBLK - 1) {
            for (int i = 0; i < NBLK; i++) g_state[i] = 0ull;
            g_ticket = 0;
            g_done = 0;
            __threadfence();
        }
    }
}

// --------- CSR fill: 4B entries (src<<16 | fp16(w*dinv[s])) ------------------
__global__ void csr_fill_kernel(const uint2* __restrict__ stage,
                                const float* __restrict__ w,
                                const float* __restrict__ dinv,
                                const int* __restrict__ rowstart,
                                unsigned* __restrict__ csru, int e) {
    int base = (blockIdx.x * blockDim.x + threadIdx.x) * 2;
    if (base >= e) return;
    uint2 st0 = stage[base];
    bool two = (base + 1 < e);
    uint2 st1 = two ? stage[base + 1] : make_uint2(0u, 0u);
    float w0 = w[base];
    float w1 = two ? w[base + 1] : 0.f;

    int s0 = (int)(st0.x & 0xFFFFu), d0 = (int)(st0.x >> 16);
    int s1 = (int)(st1.x & 0xFFFFu), d1 = (int)(st1.x >> 16);
    float ds0 = dinv[s0];
    float ds1 = two ? dinv[s1] : 0.f;
    int rs0 = rowstart[d0];
    int rs1 = two ? rowstart[d1] : 0;

    __half h0 = __float2half_rn(w0 * ds0);
    csru[rs0 + (int)st0.y] = ((unsigned)s0 << 16) | (unsigned)__half_as_ushort(h0);
    if (two) {
        __half h1 = __float2half_rn(w1 * ds1);
        csru[rs1 + (int)st1.y] =
            ((unsigned)s1 << 16) | (unsigned)__half_as_ushort(h1);
    }
}

// ---------------- CSR gather over fp16 features, fp32 accumulate -------------
__device__ __forceinline__ float4 h4_to_f4(uint2 u) {
    __half2 a = *(__half2*)&u.x;
    __half2 b = *(__half2*)&u.y;
    float2 fa = __half22float2(a);
    float2 fb = __half22float2(b);
    return make_float4(fa.x, fa.y, fb.x, fb.y);
}

__device__ __forceinline__ float csr_nrm(unsigned eent) {
    return __half2float(__ushort_as_half((unsigned short)(eent & 0xFFFFu)));
}

// DO_LN=0: write fp16 (outb = __half*). DO_LN=1: LN, write fp32 (outb = float*)
template <int DO_LN>
__global__ __launch_bounds__(256)
void gather_kernel(const int* __restrict__ rowstart,
                   const unsigned* __restrict__ csru,
                   const float* __restrict__ dinv,
                   const __half* __restrict__ feat,
                   const float* __restrict__ b2,
                   const float* __restrict__ gamma,
                   const float* __restrict__ beta,
                   void* __restrict__ outb, int n) {
    const int node = (blockIdx.x * blockDim.x + threadIdx.x) >> 5;
    const int lane = threadIdx.x & 31;
    if (node >= n) return;

    const uint2* fp = (const uint2*)feat;   // row = 32 uint2
    float dv = dinv[node];
    float4 acc = h4_to_f4(fp[node * 32 + lane]);
    acc.x *= dv; acc.y *= dv; acc.z *= dv; acc.w *= dv;

    const int beg = rowstart[node];
    const int end = rowstart[node + 1];

    int j = beg;
    for (; j + 3 < end; j += 4) {
        unsigned e0 = csru[j], e1 = csru[j + 1];
        unsigned e2 = csru[j + 2], e3 = csru[j + 3];
        uint2 r0 = fp[(e0 >> 16) * 32 + lane];
        uint2 r1 = fp[(e1 >> 16) * 32 + lane];
        uint2 r2 = fp[(e2 >> 16) * 32 + lane];
        uint2 r3 = fp[(e3 >> 16) * 32 + lane];
        float4 v0 = h4_to_f4(r0), v1 = h4_to_f4(r1);
        float4 v2 = h4_to_f4(r2), v3 = h4_to_f4(r3);
        float n0 = csr_nrm(e0), n1 = csr_nrm(e1);
        float n2 = csr_nrm(e2), n3 = csr_nrm(e3);
        acc.x = fmaf(v0.x, n0, acc.x); acc.y = fmaf(v0.y, n0, acc.y);
        acc.z = fmaf(v0.z, n0, acc.z); acc.w = fmaf(v0.w, n0, acc.w);
        acc.x = fmaf(v1.x, n1, acc.x); acc.y = fmaf(v1.y, n1, acc.y);
        acc.z = fmaf(v1.z, n1, acc.z); acc.w = fmaf(v1.w, n1, acc.w);
        acc.x = fmaf(v2.x, n2, acc.x); acc.y = fmaf(v2.y, n2, acc.y);
        acc.z = fmaf(v2.z, n2, acc.z); acc.w = fmaf(v2.w, n2, acc.w);
        acc.x = fmaf(v3.x, n3, acc.x); acc.y = fmaf(v3.y, n3, acc.y);
        acc.z = fmaf(v3.z, n3, acc.z); acc.w = fmaf(v3.w, n3, acc.w);
    }
    for (; j < end; j++) {
        unsigned e0 = csru[j];
        float4 v0 = h4_to_f4(fp[(e0 >> 16) * 32 + lane]);
        float n0 = csr_nrm(e0);
        acc.x = fmaf(v0.x, n0, acc.x); acc.y = fmaf(v0.y, n0, acc.y);
        acc.z = fmaf(v0.z, n0, acc.z); acc.w = fmaf(v0.w, n0, acc.w);
    }

    acc.x *= dv; acc.y *= dv; acc.z *= dv; acc.w *= dv;

    if (DO_LN) {
        float4 bb = *(const float4*)(b2 + lane * 4);
        acc.x += bb.x; acc.y += bb.y; acc.z += bb.z; acc.w += bb.w;

        float s = acc.x + acc.y + acc.z + acc.w;
#pragma unroll
        for (int o = 16; o > 0; o >>= 1) s += __shfl_xor_sync(0xFFFFFFFFu, s, o);
        float mu = s * (1.0f / DIN);

        float dx = acc.x - mu, dy = acc.y - mu, dz = acc.z - mu, dw = acc.w - mu;
        float q = dx * dx + dy * dy + dz * dz + dw * dw;
#pragma unroll
        for (int o = 16; o > 0; o >>= 1) q += __shfl_xor_sync(0xFFFFFFFFu, q, o);
        float rstd = rsqrtf(q * (1.0f / DIN) + 1e-5f);

        float4 g  = *(const float4*)(gamma + lane * 4);
        float4 bt = *(const float4*)(beta + lane * 4);
        float4 o4;
        o4.x = dx * rstd * g.x + bt.x;
        o4.y = dy * rstd * g.y + bt.y;
        o4.z = dz * rstd * g.z + bt.z;
        o4.w = dw * rstd * g.w + bt.w;
        *(float4*)((float*)outb + (size_t)node * DIN + lane * 4) = o4;
    } else {
        __half2 h0 = __floats2half2_rn(acc.x, acc.y);
        __half2 h1 = __floats2half2_rn(acc.z, acc.w);
        uint2 pkt = make_uint2(*(uint32_t*)&h0, *(uint32_t*)&h1);
        ((uint2*)outb)[node * 32 + lane] = pkt;
    }
}

// ---------------- fused MLP: p = relu(A@W1^T + b1) @ W2^T --------------------
__device__ __forceinline__ void mma_f16(float c[4], const uint32_t a[4],
                                        const uint32_t b[2]) {
    asm volatile(
        "mma.sync.aligned.m16n8k16.row.col.f32.f16.f16.f32 "
        "{%0,%1,%2,%3}, {%4,%5,%6,%7}, {%8,%9}, {%0,%1,%2,%3};"
        : "+f"(c[0]), "+f"(c[1]), "+f"(c[2]), "+f"(c[3])
        : "r"(a[0]), "r"(a[1]), "r"(a[2]), "r"(a[3]), "r"(b[0]), "r"(b[1]));
}

#define AS_ST 68    // uints per row (64 data + 4 pad): 128-half rows
#define W2_ST 132   // uints per row (128 data + 4 pad): 256-half rows
#define SM_A  0
#define SM_W  (SM_A + 128 * AS_ST)
#define SM_H  (SM_W + 128 * W2_ST)
#define SM_TOTAL_U (SM_H + 128 * W2_ST)

__global__ __launch_bounds__(256, 1)
void fused_mlp_kernel(const __half* __restrict__ A,
                      const __half* __restrict__ W1,
                      const __half* __restrict__ W2,
                      const float* __restrict__ b1,
                      __half* __restrict__ P, int M) {
    extern __shared__ uint32_t sm[];
    uint32_t* A_s = sm + SM_A;
    uint32_t* W_s = sm + SM_W;
    uint32_t* H_s = sm + SM_H;

    const int tid  = threadIdx.x;
    const int lane = tid & 31;
    const int warp = tid >> 5;
    const int wm   = warp & 3;
    const int wn   = warp >> 2;
    const int gid  = lane >> 2;
    const int tig  = lane & 3;
    const int m0   = blockIdx.x * 128;

#pragma unroll
    for (int l = 0; l < 8; l++) {
        int idx = tid + l * 256;
        int row = idx >> 4;
        int q   = idx & 15;
        uint4 v = (m0 + row < M)
                ? *(const uint4*)(A + (size_t)(m0 + row) * DIN + q * 8)
                : make_uint4(0u, 0u, 0u, 0u);
        *(uint4*)&A_s[row * AS_ST + q * 4] = v;
    }

    for (int nh = 0; nh < 2; nh++) {
#pragma unroll
        for (int l = 0; l < 8; l++) {
            int idx = tid + l * 256;
            int row = idx >> 4;
            int q   = idx & 15;
            uint4 v = *(const uint4*)(W1 + (size_t)(nh * 128 + row) * DIN + q * 8);
            *(uint4*)&W_s[row * AS_ST + q * 4] = v;
        }
        __syncthreads();

        float acc[2][8][4];
#pragma unroll
        for (int i = 0; i < 2; i++)
#pragma unroll
            for (int j = 0; j < 8; j++)
#pragma unroll
                for (int q = 0; q < 4; q++) acc[i][j][q] = 0.f;

#pragma unroll
        for (int s = 0; s < 8; s++) {
            const int k2 = s * 8;
            uint32_t af[2][4];
#pragma unroll
            for (int mt = 0; mt < 2; mt++) {
                int rb = wm * 32 + mt * 16;
                af[mt][0] = A_s[(rb + gid) * AS_ST + k2 + tig];
                af[mt][1] = A_s[(rb + gid + 8) * AS_ST + k2 + tig];
                af[mt][2] = A_s[(rb + gid) * AS_ST + k2 + tig + 4];
                af[mt][3] = A_s[(rb + gid + 8) * AS_ST + k2 + tig + 4];
            }
            uint32_t bf[8][2];
#pragma unroll
            for (int ntl = 0; ntl < 8; ntl++) {
                int col = wn * 64 + ntl * 8 + gid;
                bf[ntl][0] = W_s[col * AS_ST + k2 + tig];
                bf[ntl][1] = W_s[col * AS_ST + k2 + tig + 4];
            }
#pragma unroll
            for (int mt = 0; mt < 2; mt++)
#pragma unroll
                for (int ntl = 0; ntl < 8; ntl++)
                    mma_f16(acc[mt][ntl], af[mt], bf[ntl]);
        }
        __syncthreads();

#pragma unroll
        for (int mt = 0; mt < 2; mt++) {
            int r0 = wm * 32 + mt * 16 + gid;
            int r1 = r0 + 8;
#pragma unroll
            for (int ntl = 0; ntl < 8; ntl++) {
                int colL = wn * 64 + ntl * 8 + tig * 2;
                int colG = nh * 128 + colL;
                float bx = b1[colG], by = b1[colG + 1];
                float2 v0 = make_float2(fmaxf(acc[mt][ntl][0] + bx, 0.f),
                                        fmaxf(acc[mt][ntl][1] + by, 0.f));
                float2 v1 = make_float2(fmaxf(acc[mt][ntl][2] + bx, 0.f),
                                        fmaxf(acc[mt][ntl][3] + by, 0.f));
                __half2 h0 = __floats2half2_rn(v0.x, v0.y);
                __half2 h1 = __floats2half2_rn(v1.x, v1.y);
                H_s[r0 * W2_ST + (colG >> 1)] = *(uint32_t*)&h0;
                H_s[r1 * W2_ST + (colG >> 1)] = *(uint32_t*)&h1;
            }
        }
    }

#pragma unroll
    for (int l = 0; l < 16; l++) {
        int idx = tid + l * 256;
        int row = idx >> 5;
        int q   = idx & 31;
        uint4 v = *(const uint4*)(W2 + (size_t)row * DH + q * 8);
        *(uint4*)&W_s[row * W2_ST + q * 4] = v;
    }
    __syncthreads();

    float acc2[2][8][4];
#pragma unroll
    for (int i = 0; i < 2; i++)
#pragma unroll
        for (int j = 0; j < 8; j++)
#pragma unroll
            for (int q = 0; q < 4; q++) acc2[i][j][q] = 0.f;

#pragma unroll
    for (int s = 0; s < 16; s++) {
        const int k2 = s * 8;
        uint32_t af[2][4];
#pragma unroll
        for (int mt = 0; mt < 2; mt++) {
            int rb = wm * 32 + mt * 16;
            af[mt][0] = H_s[(rb + gid) * W2_ST + k2 + tig];
            af[mt][1] = H_s[(rb + gid + 8) * W2_ST + k2 + tig];
            af[mt][2] = H_s[(rb + gid) * W2_ST + k2 + tig + 4];
            af[mt][3] = H_s[(rb + gid + 8) * W2_ST + k2 + tig + 4];
        }
        uint32_t bf[8][2];
#pragma unroll
        for (int ntl = 0; ntl < 8; ntl++) {
            int col = wn * 64 + ntl * 8 + gid;
            bf[ntl][0] = W_s[col * W2_ST + k2 + tig];
            bf[ntl][1] = W_s[col * W2_ST + k2 + tig + 4];
        }
#pragma unroll
        for (int mt = 0; mt < 2; mt++)
#pragma unroll
            for (int ntl = 0; ntl < 8; ntl++)
                mma_f16(acc2[mt][ntl], af[mt], bf[ntl]);
    }

#pragma unroll
    for (int mt = 0; mt < 2; mt++) {
        int row0 = m0 + wm * 32 + mt * 16 + gid;
        int row1 = row0 + 8;
#pragma unroll
        for (int ntl = 0; ntl < 8; ntl++) {
            int col = wn * 64 + ntl * 8 + tig * 2;
            __half2 h0 = __floats2half2_rn(acc2[mt][ntl][0], acc2[mt][ntl][1]);
            __half2 h1 = __floats2half2_rn(acc2[mt][ntl][2], acc2[mt][ntl][3]);
            if (row0 < M) *(__half2*)(P + (size_t)row0 * DIN + col) = h0;
            if (row1 < M) *(__half2*)(P + (size_t)row1 * DIN + col) = h1;
        }
    }
}

// -----------------------------------------------------------------------------
extern "C" void kernel_launch(void* const* d_in, const int* in_sizes, int n_in,
                              void* d_out, int out_size) {
    const float* x     = (const float*)d_in[0];
    const void*  ei    = d_in[1];
    const float* ew    = (const float*)d_in[2];
    const float* W1    = (const float*)d_in[3];
    const float* b1    = (const float*)d_in[4];
    const float* W2    = (const float*)d_in[5];
    const float* b2    = (const float*)d_in[6];
    const float* gamma = (const float*)d_in[7];
    const float* beta  = (const float*)d_in[8];
    float*       out   = (float*)d_out;

    float *dinv;
    __half *xh, *a1h, *ph, *w1h, *w2h;
    int *rowstart;
    uint2 *stage;
    unsigned *csru;
    unsigned long long *pk;
    cudaGetSymbolAddress((void**)&pk,       g_packed);
    cudaGetSymbolAddress((void**)&dinv,     g_dinv);
    cudaGetSymbolAddress((void**)&xh,       g_xh);
    cudaGetSymbolAddress((void**)&a1h,      g_a1h);
    cudaGetSymbolAddress((void**)&ph,       g_ph);
    cudaGetSymbolAddress((void**)&w1h,      g_w1h);
    cudaGetSymbolAddress((void**)&w2h,      g_w2h);
    cudaGetSymbolAddress((void**)&rowstart, g_rowstart);
    cudaGetSymbolAddress((void**)&stage,    g_stage);
    cudaGetSymbolAddress((void**)&csru,     g_csru);

    const int n = NN, e = EE;
    const int smem_bytes = SM_TOTAL_U * 4;
    static bool attr_set = false;
    if (!attr_set) {
        cudaFuncSetAttribute(fused_mlp_kernel,
                             cudaFuncAttributeMaxDynamicSharedMemorySize,
                             smem_bytes);
        attr_set = true;
    }

    // 1. conversions + packed degree/count/rank staging (fused)
    convert_prep_kernel<<<1566, 256>>>(ei, ew, x, W1, W2, pk, stage, e);

    // 2. single-pass scan (+dinv, self-resetting state)
    scan_lookback_kernel<<<NBLK, 256>>>(pk, dinv, rowstart, n);

    // 3. CSR fill (4B entries)
    csr_fill_kernel<<<(e / 2 + 255) / 256, 256>>>(stage, ew, dinv, rowstart,
                                                  csru, e);

    // 4. agg1 = A_norm @ x  (warp-per-node fp16 gather -> fp16)
    gather_kernel<0><<<(n * 32 + 255) / 256, 256>>>(rowstart, csru, dinv, xh,
                                                    nullptr, nullptr, nullptr,
                                                    a1h, n);

    // 5. p = relu(agg1 @ W1^T + b1) @ W2^T   (fused MLP)
    fused_mlp_kernel<<<(n + 127) / 128, 256, smem_bytes>>>(a1h, w1h, w2h, b1,
                                                           ph, n);

    // 6. out = LN(A_norm @ p + b2) * gamma + beta
    gather_kernel<1><<<(n * 32 + 255) / 256, 256>>>(rowstart, csru, dinv, ph,
                                                    b2, gamma, beta, out, n);
}